// round 6
// baseline (speedup 1.0000x reference)
#include <cuda_runtime.h>
#include <cuda_fp16.h>
#include <cstdint>

// ---------------- problem constants ----------------
constexpr int KC = 128, KH = 10, KW = 4;
constexpr int H = 100, W = 64;
constexpr int NH = 10, NW = 16;
constexpr int M = NH * NW;                 // 160 q rows
constexpr int MPAD = 256;                  // 2 tiles of 128 (rows 160..255 zero)
constexpr int HK = H - KH + 1;             // 91
constexpr int WK = W - KW + 1;             // 61
constexpr int NKV = HK * WK;               // 5551
constexpr int NPAD = 5632;                 // 44*128
constexpr int D = KC * KH * KW;            // 5120

constexpr int S1 = 5;                      // split-K for q@kv^T  (80 BK-iters -> 16 each)
constexpr int S2 = 4;                      // split-K for attn@kv (88 BK-iters -> 22 each)

// ---------------- scratch ----------------
__device__ __half g_kv [(size_t)NPAD * D];          // [n][d] d-contig
__device__ __half g_q  [(size_t)MPAD * D];          // rows >=160 stay zero
__device__ __half g_attn[(size_t)MPAD * NPAD];      // rows >=160 stay zero
__device__ float  g_scp [S1][(size_t)MPAD * NPAD];  // score partials
__device__ float  g_outp[S2][(size_t)MPAD * D];     // out partials

// ---------------- ptx helpers ----------------
__device__ __forceinline__ uint32_t smem_u32(const void* p) {
    return (uint32_t)__cvta_generic_to_shared(p);
}
__device__ __forceinline__ void ldsm_x4(uint32_t& r0, uint32_t& r1, uint32_t& r2,
                                        uint32_t& r3, uint32_t a) {
    asm volatile("ldmatrix.sync.aligned.m8n8.x4.shared.b16 {%0,%1,%2,%3}, [%4];"
                 : "=r"(r0), "=r"(r1), "=r"(r2), "=r"(r3) : "r"(a));
}
__device__ __forceinline__ void ldsm_x4_t(uint32_t& r0, uint32_t& r1, uint32_t& r2,
                                          uint32_t& r3, uint32_t a) {
    asm volatile("ldmatrix.sync.aligned.m8n8.x4.trans.shared.b16 {%0,%1,%2,%3}, [%4];"
                 : "=r"(r0), "=r"(r1), "=r"(r2), "=r"(r3) : "r"(a));
}
__device__ __forceinline__ void mma16816(float* c, const uint32_t* a, const uint32_t* b) {
    asm volatile("mma.sync.aligned.m16n8k16.row.col.f32.f16.f16.f32 "
                 "{%0,%1,%2,%3}, {%4,%5,%6,%7}, {%8,%9}, {%0,%1,%2,%3};"
                 : "+f"(c[0]), "+f"(c[1]), "+f"(c[2]), "+f"(c[3])
                 : "r"(a[0]), "r"(a[1]), "r"(a[2]), "r"(a[3]),
                   "r"(b[0]), "r"(b[1]));
}
__device__ __forceinline__ void cpasync16(uint32_t s, const void* g) {
    asm volatile("cp.async.cg.shared.global [%0], [%1], 16;" :: "r"(s), "l"(g));
}
#define CP_COMMIT() asm volatile("cp.async.commit_group;")
#define CP_WAIT(n)  asm volatile("cp.async.wait_group %0;" :: "n"(n))

// ---------------- kernel 1: expand z2 -> kv fp16 ----------------
__global__ void build_kv_kernel(const float* __restrict__ z2) {
    constexpr int TOTAL = NKV * KC * KH;
    constexpr int PADG  = (NPAD - NKV) * (D / 4);
    int idx = blockIdx.x * blockDim.x + threadIdx.x;
    if (idx < TOTAL) {
        int n   = idx / (KC * KH);
        int rem = idx - n * (KC * KH);
        int c   = rem / KH;
        int i   = rem - c * KH;
        int h   = n / WK;
        int w   = n - h * WK;
        const float* src = z2 + (c * H + h + i) * W + w;
        __half2 p0 = __floats2half2_rn(src[0], src[1]);
        __half2 p1 = __floats2half2_rn(src[2], src[3]);
        uint2 v;
        v.x = *reinterpret_cast<uint32_t*>(&p0);
        v.y = *reinterpret_cast<uint32_t*>(&p1);
        *reinterpret_cast<uint2*>(&g_kv[(size_t)n * D + (c * KH + i) * KW]) = v;
    } else if (idx < TOTAL + PADG) {
        int p   = idx - TOTAL;
        int pr  = p / (D / 4);
        int off = (p - pr * (D / 4)) * 4;
        *reinterpret_cast<uint2*>(&g_kv[(size_t)(NKV + pr) * D + off]) = make_uint2(0u, 0u);
    }
}

// ---------------- kernel 2: q patches -> fp16 ----------------
__global__ void build_q_kernel(const float* __restrict__ z1) {
    constexpr int TOTAL = M * KC * KH;
    int idx = blockIdx.x * blockDim.x + threadIdx.x;
    if (idx >= TOTAL) return;
    int m   = idx / (KC * KH);
    int rem = idx - m * (KC * KH);
    int c   = rem / KH;
    int i   = rem - c * KH;
    int ih  = m >> 4;
    int iw  = m & 15;
    const float4 f = *reinterpret_cast<const float4*>(
        z1 + (c * H + ih * KH + i) * W + iw * KW);
    __half2 p0 = __floats2half2_rn(f.x, f.y);
    __half2 p1 = __floats2half2_rn(f.z, f.w);
    uint2 v;
    v.x = *reinterpret_cast<uint32_t*>(&p0);
    v.y = *reinterpret_cast<uint32_t*>(&p1);
    *reinterpret_cast<uint2*>(&g_q[(size_t)m * D + (c * KH + i) * KW]) = v;
}

// ---------------- GEMM tiling: 128x128 CTA, 4 warps (64x64 each) ----------------
constexpr int GBM = 128, GBN = 128, GBK = 64;
constexpr int LDSA = 72;                         // k-contig rows (64 halves + pad)
constexpr int LDSB = 136;                        // av B rows (128 halves + pad)
constexpr int A_H  = GBM * LDSA;                 // 9216
constexpr int B1_H = GBN * LDSA;                 // 9216
constexpr int STG_H = A_H + B1_H;                // 18432 halves (covers both kernels)
constexpr int STAGES = 3;
constexpr int SMEM_BYTES = STAGES * STG_H * 2;   // 110592

// ---------------- kernel 3: score partials = q @ kv^T (split-K) ----------------
__global__ __launch_bounds__(128, 2) void gemm_qk_kernel() {
    extern __shared__ __align__(16) __half sm[];
    const int n0    = blockIdx.x * GBN;
    const int m0    = blockIdx.y * GBM;
    const int split = blockIdx.z;
    const int kbase = split * (D / GBK / S1);    // in BK units (16 each)
    constexpr int KT = D / GBK / S1;             // 16
    const int tid  = threadIdx.x;
    const int warp = tid >> 5, lane = tid & 31;
    const int wm = warp >> 1, wn = warp & 1;

    auto load_stage = [&](int s, int kt) {
        const int k0 = (kbase + kt) * GBK;
        __half* As = sm + s * STG_H;
        __half* Bs = As + A_H;
#pragma unroll
        for (int i = 0; i < 8; i++) {            // 1024 A chunks
            int t = tid + i * 128;
            int r = t >> 3, c8 = (t & 7) << 3;
            cpasync16(smem_u32(&As[r * LDSA + c8]),
                      &g_q[(size_t)(m0 + r) * D + k0 + c8]);
        }
#pragma unroll
        for (int i = 0; i < 8; i++) {            // 1024 B chunks
            int t = tid + i * 128;
            int r = t >> 3, c8 = (t & 7) << 3;
            cpasync16(smem_u32(&Bs[r * LDSA + c8]),
                      &g_kv[(size_t)(n0 + r) * D + k0 + c8]);
        }
    };

    load_stage(0, 0); CP_COMMIT();
    load_stage(1, 1); CP_COMMIT();

    float acc[4][8][4] = {};

    for (int kt = 0; kt < KT; kt++) {
        if (kt < KT - 2) { CP_WAIT(1); } else { CP_WAIT(0); }
        __syncthreads();
        const int nxt = kt + 2;
        if (nxt < KT) { load_stage(nxt % 3, nxt); CP_COMMIT(); }

        const __half* As = sm + (kt % 3) * STG_H;
        const __half* Bs = As + A_H;
#pragma unroll
        for (int ks = 0; ks < GBK / 16; ks++) {
            uint32_t a[4][4], b[8][2];
#pragma unroll
            for (int mt = 0; mt < 4; mt++) {
                int r = wm * 64 + mt * 16 + (lane & 15);
                int c = ks * 16 + (lane >> 4) * 8;
                ldsm_x4(a[mt][0], a[mt][1], a[mt][2], a[mt][3],
                        smem_u32(&As[r * LDSA + c]));
            }
#pragma unroll
            for (int nb = 0; nb < 4; nb++) {
                int r = wn * 64 + nb * 16 + (lane & 7) + (lane >> 4) * 8;
                int c = ks * 16 + ((lane >> 3) & 1) * 8;
                uint32_t r0, r1, r2, r3;
                ldsm_x4(r0, r1, r2, r3, smem_u32(&Bs[r * LDSA + c]));
                b[nb * 2][0] = r0; b[nb * 2][1] = r1;
                b[nb * 2 + 1][0] = r2; b[nb * 2 + 1][1] = r3;
            }
#pragma unroll
            for (int mt = 0; mt < 4; mt++)
#pragma unroll
                for (int nc = 0; nc < 8; nc++)
                    mma16816(acc[mt][nc], a[mt], b[nc]);
        }
    }

    float* scp = g_scp[split];
#pragma unroll
    for (int mt = 0; mt < 4; mt++)
#pragma unroll
        for (int nc = 0; nc < 8; nc++) {
            int row = m0 + wm * 64 + mt * 16 + (lane >> 2);
            int col = n0 + wn * 64 + nc * 8 + ((lane & 3) << 1);
            scp[(size_t)row * NPAD + col]           = acc[mt][nc][0];
            scp[(size_t)row * NPAD + col + 1]       = acc[mt][nc][1];
            scp[(size_t)(row + 8) * NPAD + col]     = acc[mt][nc][2];
            scp[(size_t)(row + 8) * NPAD + col + 1] = acc[mt][nc][3];
        }
}

// ---------------- kernel 4: softmax over summed partials ----------------
__global__ __launch_bounds__(512) void softmax_kernel() {
    __shared__ float row[NPAD];
    __shared__ float red[512];
    const int m   = blockIdx.x;
    const int tid = threadIdx.x;
    const float scale = 1.0f / (float)D;

    float mx = -1e30f;
    for (int n = tid; n < NKV; n += 512) {
        float v = 0.f;
#pragma unroll
        for (int s = 0; s < S1; s++) v += g_scp[s][(size_t)m * NPAD + n];
        v *= scale;
        row[n] = v;
        mx = fmaxf(mx, v);
    }
    red[tid] = mx;
    __syncthreads();
    for (int s = 256; s > 0; s >>= 1) {
        if (tid < s) red[tid] = fmaxf(red[tid], red[tid + s]);
        __syncthreads();
    }
    const float smx = red[0];
    __syncthreads();

    float sum = 0.f;
    for (int n = tid; n < NKV; n += 512) {
        float e = __expf(row[n] - smx);
        row[n] = e;
        sum += e;
    }
    red[tid] = sum;
    __syncthreads();
    for (int s = 256; s > 0; s >>= 1) {
        if (tid < s) red[tid] += red[tid + s];
        __syncthreads();
    }
    const float inv = 1.0f / red[0];
    for (int n = tid; n < NPAD; n += 512)
        g_attn[(size_t)m * NPAD + n] = (n < NKV) ? __float2half(row[n] * inv)
                                                 : __float2half(0.f);
}

// ---------------- kernel 5: out partials = attn @ kv (split-K) ----------------
__global__ __launch_bounds__(128, 2) void gemm_av_kernel() {
    extern __shared__ __align__(16) __half sm[];
    const int n0    = blockIdx.x * GBN;          // over D
    const int m0    = blockIdx.y * GBM;
    const int split = blockIdx.z;
    constexpr int KT = NPAD / GBK / S2;          // 22
    const int kbase = split * KT;
    const int tid  = threadIdx.x;
    const int warp = tid >> 5, lane = tid & 31;
    const int wm = warp >> 1, wn = warp & 1;

    auto load_stage = [&](int s, int kt) {
        const int k0 = (kbase + kt) * GBK;
        __half* As = sm + s * STG_H;
        __half* Bs = As + A_H;
#pragma unroll
        for (int i = 0; i < 8; i++) {            // A: 128 rows x 8 chunks (k-contig)
            int t = tid + i * 128;
            int r = t >> 3, c8 = (t & 7) << 3;
            cpasync16(smem_u32(&As[r * LDSA + c8]),
                      &g_attn[(size_t)(m0 + r) * NPAD + k0 + c8]);
        }
#pragma unroll
        for (int i = 0; i < 8; i++) {            // B: 64 k-rows x 16 chunks (n-contig)
            int t = tid + i * 128;
            int r = t >> 4, c8 = (t & 15) << 3;
            cpasync16(smem_u32(&Bs[r * LDSB + c8]),
                      &g_kv[(size_t)(k0 + r) * D + n0 + c8]);
        }
    };

    load_stage(0, 0); CP_COMMIT();
    load_stage(1, 1); CP_COMMIT();

    float acc[4][8][4] = {};

    for (int kt = 0; kt < KT; kt++) {
        if (kt < KT - 2) { CP_WAIT(1); } else { CP_WAIT(0); }
        __syncthreads();
        const int nxt = kt + 2;
        if (nxt < KT) { load_stage(nxt % 3, nxt); CP_COMMIT(); }

        const __half* As = sm + (kt % 3) * STG_H;
        const __half* Bs = As + A_H;
#pragma unroll
        for (int ks = 0; ks < GBK / 16; ks++) {
            uint32_t a[4][4], b[8][2];
#pragma unroll
            for (int mt = 0; mt < 4; mt++) {
                int r = wm * 64 + mt * 16 + (lane & 15);
                int c = ks * 16 + (lane >> 4) * 8;
                ldsm_x4(a[mt][0], a[mt][1], a[mt][2], a[mt][3],
                        smem_u32(&As[r * LDSA + c]));
            }
#pragma unroll
            for (int nb = 0; nb < 4; nb++) {
                int r = ks * 16 + (lane & 7) + ((lane >> 3) & 1) * 8;
                int c = wn * 64 + nb * 16 + (lane >> 4) * 8;
                uint32_t r0, r1, r2, r3;
                ldsm_x4_t(r0, r1, r2, r3, smem_u32(&Bs[r * LDSB + c]));
                b[nb * 2][0] = r0; b[nb * 2][1] = r1;
                b[nb * 2 + 1][0] = r2; b[nb * 2 + 1][1] = r3;
            }
#pragma unroll
            for (int mt = 0; mt < 4; mt++)
#pragma unroll
                for (int nc = 0; nc < 8; nc++)
                    mma16816(acc[mt][nc], a[mt], b[nc]);
        }
    }

    float* op = g_outp[split];
#pragma unroll
    for (int mt = 0; mt < 4; mt++)
#pragma unroll
        for (int nc = 0; nc < 8; nc++) {
            int row = m0 + wm * 64 + mt * 16 + (lane >> 2);
            int col = n0 + wn * 64 + nc * 8 + ((lane & 3) << 1);
            op[(size_t)row * D + col]           = acc[mt][nc][0];
            op[(size_t)row * D + col + 1]       = acc[mt][nc][1];
            op[(size_t)(row + 8) * D + col]     = acc[mt][nc][2];
            op[(size_t)(row + 8) * D + col + 1] = acc[mt][nc][3];
        }
}

// ---------------- kernel 6: sum out partials + remap ----------------
__global__ __launch_bounds__(256) void reduce_out_kernel(float* __restrict__ out) {
    constexpr int G = D / 4;                     // 1280 float4 groups per row
    int idx = blockIdx.x * blockDim.x + threadIdx.x;
    if (idx >= M * G) return;
    int m = idx / G;
    int g = idx - m * G;
    int d = g * 4;
    float4 v = make_float4(0.f, 0.f, 0.f, 0.f);
#pragma unroll
    for (int s = 0; s < S2; s++) {
        float4 p = *reinterpret_cast<const float4*>(&g_outp[s][(size_t)m * D + d]);
        v.x += p.x; v.y += p.y; v.z += p.z; v.w += p.w;
    }
    int c   = d / 40;
    int rem = d - c * 40;
    int i   = rem >> 2;              // rem multiple of 4 -> j = 0
    int ih  = m >> 4;
    int iw  = m & 15;
    *reinterpret_cast<float4*>(&out[(c * H + ih * KH + i) * W + iw * KW]) = v;
}

// ---------------- launch ----------------
extern "C" void kernel_launch(void* const* d_in, const int* in_sizes, int n_in,
                              void* d_out, int out_size) {
    const float* z1 = (const float*)d_in[0];
    const float* z2 = (const float*)d_in[1];
    float* out = (float*)d_out;

    cudaFuncSetAttribute(gemm_qk_kernel,
                         cudaFuncAttributeMaxDynamicSharedMemorySize, SMEM_BYTES);
    cudaFuncSetAttribute(gemm_av_kernel,
                         cudaFuncAttributeMaxDynamicSharedMemorySize, SMEM_BYTES);

    build_q_kernel<<<800, 256>>>(z1);
    build_kv_kernel<<<28160, 256>>>(z2);
    gemm_qk_kernel<<<dim3(NPAD / GBN, MPAD / GBM, S1), 128, SMEM_BYTES>>>(); // 44x2x5
    softmax_kernel<<<M, 512>>>();
    gemm_av_kernel<<<dim3(D / GBN, MPAD / GBM, S2), 128, SMEM_BYTES>>>();    // 40x2x4
    reduce_out_kernel<<<(M * (D / 4) + 255) / 256, 256>>>(out);
}

// round 7
// speedup vs baseline: 1.0155x; 1.0155x over previous
#include <cuda_runtime.h>
#include <cuda_fp16.h>
#include <cstdint>

// ---------------- problem constants ----------------
constexpr int KC = 128, KH = 10, KW = 4;
constexpr int H = 100, W = 64;
constexpr int NH = 10, NW = 16;
constexpr int M = NH * NW;                 // 160 q rows (no padding!)
constexpr int HK = H - KH + 1;             // 91
constexpr int WK = W - KW + 1;             // 61
constexpr int NKV = HK * WK;               // 5551
constexpr int NPAD = 5632;                 // 88*64
constexpr int D = KC * KH * KW;            // 5120

// ---------------- scratch ----------------
__device__ __half g_kv[(size_t)NPAD * D];      // [n][d] d-contig
__device__ __half g_q[M * D];
__device__ float  g_scores[M * NPAD];
__device__ __half g_attn[M * NPAD];

// ---------------- ptx helpers ----------------
__device__ __forceinline__ uint32_t smem_u32(const void* p) {
    return (uint32_t)__cvta_generic_to_shared(p);
}
__device__ __forceinline__ void ldsm_x4(uint32_t& r0, uint32_t& r1, uint32_t& r2,
                                        uint32_t& r3, uint32_t a) {
    asm volatile("ldmatrix.sync.aligned.m8n8.x4.shared.b16 {%0,%1,%2,%3}, [%4];"
                 : "=r"(r0), "=r"(r1), "=r"(r2), "=r"(r3) : "r"(a));
}
__device__ __forceinline__ void ldsm_x4_t(uint32_t& r0, uint32_t& r1, uint32_t& r2,
                                          uint32_t& r3, uint32_t a) {
    asm volatile("ldmatrix.sync.aligned.m8n8.x4.trans.shared.b16 {%0,%1,%2,%3}, [%4];"
                 : "=r"(r0), "=r"(r1), "=r"(r2), "=r"(r3) : "r"(a));
}
__device__ __forceinline__ void mma16816(float* c, const uint32_t* a, const uint32_t* b) {
    asm volatile("mma.sync.aligned.m16n8k16.row.col.f32.f16.f16.f32 "
                 "{%0,%1,%2,%3}, {%4,%5,%6,%7}, {%8,%9}, {%0,%1,%2,%3};"
                 : "+f"(c[0]), "+f"(c[1]), "+f"(c[2]), "+f"(c[3])
                 : "r"(a[0]), "r"(a[1]), "r"(a[2]), "r"(a[3]),
                   "r"(b[0]), "r"(b[1]));
}
__device__ __forceinline__ void cpasync16(uint32_t s, const void* g) {
    asm volatile("cp.async.cg.shared.global [%0], [%1], 16;" :: "r"(s), "l"(g));
}
#define CP_COMMIT() asm volatile("cp.async.commit_group;")
#define CP_WAIT(n)  asm volatile("cp.async.wait_group %0;" :: "n"(n))

// ---------------- kernel 1: expand z2 -> kv fp16 ----------------
__global__ void build_kv_kernel(const float* __restrict__ z2) {
    constexpr int TOTAL = NKV * KC * KH;
    constexpr int PADG  = (NPAD - NKV) * (D / 4);
    int idx = blockIdx.x * blockDim.x + threadIdx.x;
    if (idx < TOTAL) {
        int n   = idx / (KC * KH);
        int rem = idx - n * (KC * KH);
        int c   = rem / KH;
        int i   = rem - c * KH;
        int h   = n / WK;
        int w   = n - h * WK;
        const float* src = z2 + (c * H + h + i) * W + w;
        __half2 p0 = __floats2half2_rn(src[0], src[1]);
        __half2 p1 = __floats2half2_rn(src[2], src[3]);
        uint2 v;
        v.x = *reinterpret_cast<uint32_t*>(&p0);
        v.y = *reinterpret_cast<uint32_t*>(&p1);
        *reinterpret_cast<uint2*>(&g_kv[(size_t)n * D + (c * KH + i) * KW]) = v;
    } else if (idx < TOTAL + PADG) {
        int p   = idx - TOTAL;
        int pr  = p / (D / 4);
        int off = (p - pr * (D / 4)) * 4;
        *reinterpret_cast<uint2*>(&g_kv[(size_t)(NKV + pr) * D + off]) = make_uint2(0u, 0u);
    }
}

// ---------------- kernel 2: q patches -> fp16 ----------------
__global__ void build_q_kernel(const float* __restrict__ z1) {
    constexpr int TOTAL = M * KC * KH;
    int idx = blockIdx.x * blockDim.x + threadIdx.x;
    if (idx >= TOTAL) return;
    int m   = idx / (KC * KH);
    int rem = idx - m * (KC * KH);
    int c   = rem / KH;
    int i   = rem - c * KH;
    int ih  = m >> 4;
    int iw  = m & 15;
    const float4 f = *reinterpret_cast<const float4*>(
        z1 + (c * H + ih * KH + i) * W + iw * KW);
    __half2 p0 = __floats2half2_rn(f.x, f.y);
    __half2 p1 = __floats2half2_rn(f.z, f.w);
    uint2 v;
    v.x = *reinterpret_cast<uint32_t*>(&p0);
    v.y = *reinterpret_cast<uint32_t*>(&p1);
    *reinterpret_cast<uint2*>(&g_q[m * D + (c * KH + i) * KW]) = v;
}

// ---------------- GEMM tiling (R3 shape + variable-M tiles) ----------------
// grid.y = 0,1 -> mf=2 (64-row tile, exact R3 path); grid.y = 2 -> mf=1 (32-row tile)
constexpr int BK  = 64;
constexpr int BN  = 64;
constexpr int LDS = 72;
constexpr int STAGES = 4;
constexpr int A_HALVES = 64 * LDS;               // sized for mf=2 (4608)
constexpr int B_HALVES = BN * LDS;               // 4608
constexpr int STAGE_HALVES = A_HALVES + B_HALVES;
constexpr int SMEM_BYTES = STAGES * STAGE_HALVES * 2;   // 73728 (== R3)

// ---------------- kernel 3: scores = (q @ kv^T) / D ----------------
__global__ __launch_bounds__(128, 3) void gemm_qk_kernel() {
    extern __shared__ __align__(16) __half sm[];
    const int n0   = blockIdx.x * BN;
    const int m0   = blockIdx.y * 64;
    const int mf   = (blockIdx.y == 2) ? 1 : 2;      // 32- or 64-row tile
    const int tid  = threadIdx.x;
    const int warp = tid >> 5, lane = tid & 31;
    const int wm = warp >> 1, wn = warp & 1;
    constexpr int KT = D / BK;                       // 80

    const int a_chunks = 32 * mf * 8;                // 256*mf int4 chunks

    auto load_stage = [&](int s, int kt) {
        const int k0 = kt * BK;
        __half* As = sm + s * STAGE_HALVES;
        __half* Bs = As + A_HALVES;
        for (int t = tid; t < a_chunks; t += 128) {
            int r = t >> 3, c8 = (t & 7) << 3;
            cpasync16(smem_u32(&As[r * LDS + c8]),
                      &g_q[(m0 + r) * D + k0 + c8]);
        }
#pragma unroll
        for (int i = 0; i < 4; i++) {                // 512 B chunks
            int t = tid + i * 128;
            int r = t >> 3, c8 = (t & 7) << 3;
            cpasync16(smem_u32(&Bs[r * LDS + c8]),
                      &g_kv[(size_t)(n0 + r) * D + k0 + c8]);
        }
    };

#pragma unroll
    for (int s = 0; s < STAGES - 1; s++) { load_stage(s, s); CP_COMMIT(); }

    float acc[2][4][4] = {};

    for (int kt = 0; kt < KT; kt++) {
        CP_WAIT(STAGES - 2);
        __syncthreads();
        int nxt = kt + STAGES - 1;
        if (nxt < KT) load_stage(nxt & (STAGES - 1), nxt);
        CP_COMMIT();

        const __half* As = sm + (kt & (STAGES - 1)) * STAGE_HALVES;
        const __half* Bs = As + A_HALVES;
#pragma unroll
        for (int ks = 0; ks < BK / 16; ks++) {
            uint32_t a[2][4], b[4][2];
#pragma unroll
            for (int mi = 0; mi < 2; mi++) {
                if (mi < mf) {
                    int r = wm * 16 * mf + mi * 16 + (lane & 15);
                    int c = ks * 16 + (lane >> 4) * 8;
                    ldsm_x4(a[mi][0], a[mi][1], a[mi][2], a[mi][3],
                            smem_u32(&As[r * LDS + c]));
                }
            }
#pragma unroll
            for (int nb = 0; nb < 2; nb++) {
                int r = wn * 32 + nb * 16 + (lane & 7) + (lane >> 4) * 8;
                int c = ks * 16 + ((lane >> 3) & 1) * 8;
                uint32_t r0, r1, r2, r3;
                ldsm_x4(r0, r1, r2, r3, smem_u32(&Bs[r * LDS + c]));
                b[nb * 2][0] = r0; b[nb * 2][1] = r1;
                b[nb * 2 + 1][0] = r2; b[nb * 2 + 1][1] = r3;
            }
#pragma unroll
            for (int mi = 0; mi < 2; mi++)
                if (mi < mf)
#pragma unroll
                    for (int ni = 0; ni < 4; ni++)
                        mma16816(acc[mi][ni], a[mi], b[ni]);
        }
    }

    const float scale = 1.0f / (float)D;
#pragma unroll
    for (int mi = 0; mi < 2; mi++) {
        if (mi >= mf) continue;
#pragma unroll
        for (int ni = 0; ni < 4; ni++) {
            int row = m0 + wm * 16 * mf + mi * 16 + (lane >> 2);
            int col = n0 + wn * 32 + ni * 8 + ((lane & 3) << 1);
            g_scores[row * NPAD + col]           = acc[mi][ni][0] * scale;
            g_scores[row * NPAD + col + 1]       = acc[mi][ni][1] * scale;
            g_scores[(row + 8) * NPAD + col]     = acc[mi][ni][2] * scale;
            g_scores[(row + 8) * NPAD + col + 1] = acc[mi][ni][3] * scale;
        }
    }
}

// ---------------- kernel 4: row softmax ----------------
__global__ __launch_bounds__(512) void softmax_kernel() {
    __shared__ float row[NPAD];
    __shared__ float red[512];
    const int m   = blockIdx.x;
    const int tid = threadIdx.x;

    float mx = -1e30f;
    for (int n = tid; n < NKV; n += 512) {
        float v = g_scores[m * NPAD + n];
        row[n] = v;
        mx = fmaxf(mx, v);
    }
    red[tid] = mx;
    __syncthreads();
    for (int s = 256; s > 0; s >>= 1) {
        if (tid < s) red[tid] = fmaxf(red[tid], red[tid + s]);
        __syncthreads();
    }
    const float smx = red[0];
    __syncthreads();

    float sum = 0.f;
    for (int n = tid; n < NKV; n += 512) {
        float e = __expf(row[n] - smx);
        row[n] = e;
        sum += e;
    }
    red[tid] = sum;
    __syncthreads();
    for (int s = 256; s > 0; s >>= 1) {
        if (tid < s) red[tid] += red[tid + s];
        __syncthreads();
    }
    const float inv = 1.0f / red[0];
    for (int n = tid; n < NPAD; n += 512)
        g_attn[m * NPAD + n] = (n < NKV) ? __float2half(row[n] * inv)
                                         : __float2half(0.f);
}

// ---------------- kernel 5: out = attn @ kv ----------------
__device__ __forceinline__ void store_out(float* __restrict__ out, int m, int d, float v) {
    int c   = d / 40;
    int rem = d - c * 40;
    int i   = rem >> 2;
    int j   = rem & 3;
    int ih  = m >> 4;
    int iw  = m & 15;
    out[(c * H + ih * KH + i) * W + iw * KW + j] = v;
}

__global__ __launch_bounds__(128, 3) void gemm_av_kernel(float* __restrict__ out) {
    extern __shared__ __align__(16) __half sm[];
    const int n0   = blockIdx.x * BN;            // over D
    const int m0   = blockIdx.y * 64;
    const int mf   = (blockIdx.y == 2) ? 1 : 2;
    const int tid  = threadIdx.x;
    const int warp = tid >> 5, lane = tid & 31;
    const int wm = warp >> 1, wn = warp & 1;
    constexpr int KT = NPAD / BK;                // 88

    const int a_chunks = 32 * mf * 8;

    auto load_stage = [&](int s, int kt) {
        const int k0 = kt * BK;
        __half* As = sm + s * STAGE_HALVES;
        __half* Bs = As + A_HALVES;
        for (int t = tid; t < a_chunks; t += 128) {
            int r = t >> 3, c8 = (t & 7) << 3;
            cpasync16(smem_u32(&As[r * LDS + c8]),
                      &g_attn[(m0 + r) * NPAD + k0 + c8]);
        }
#pragma unroll
        for (int i = 0; i < 4; i++) {
            int t = tid + i * 128;
            int r = t >> 3, c8 = (t & 7) << 3;
            cpasync16(smem_u32(&Bs[r * LDS + c8]),
                      &g_kv[(size_t)(k0 + r) * D + n0 + c8]);
        }
    };

#pragma unroll
    for (int s = 0; s < STAGES - 1; s++) { load_stage(s, s); CP_COMMIT(); }

    float acc[2][4][4] = {};

    for (int kt = 0; kt < KT; kt++) {
        CP_WAIT(STAGES - 2);
        __syncthreads();
        int nxt = kt + STAGES - 1;
        if (nxt < KT) load_stage(nxt & (STAGES - 1), nxt);
        CP_COMMIT();

        const __half* As = sm + (kt & (STAGES - 1)) * STAGE_HALVES;
        const __half* Bs = As + A_HALVES;
#pragma unroll
        for (int ks = 0; ks < BK / 16; ks++) {
            uint32_t a[2][4], b[4][2];
#pragma unroll
            for (int mi = 0; mi < 2; mi++) {
                if (mi < mf) {
                    int r = wm * 16 * mf + mi * 16 + (lane & 15);
                    int c = ks * 16 + (lane >> 4) * 8;
                    ldsm_x4(a[mi][0], a[mi][1], a[mi][2], a[mi][3],
                            smem_u32(&As[r * LDS + c]));
                }
            }
#pragma unroll
            for (int nb = 0; nb < 2; nb++) {
                int r = ks * 16 + (lane & 7) + ((lane >> 3) & 1) * 8;
                int c = wn * 32 + nb * 16 + (lane >> 4) * 8;
                uint32_t r0, r1, r2, r3;
                ldsm_x4_t(r0, r1, r2, r3, smem_u32(&Bs[r * LDS + c]));
                b[nb * 2][0] = r0; b[nb * 2][1] = r1;
                b[nb * 2 + 1][0] = r2; b[nb * 2 + 1][1] = r3;
            }
#pragma unroll
            for (int mi = 0; mi < 2; mi++)
                if (mi < mf)
#pragma unroll
                    for (int ni = 0; ni < 4; ni++)
                        mma16816(acc[mi][ni], a[mi], b[ni]);
        }
    }

#pragma unroll
    for (int mi = 0; mi < 2; mi++) {
        if (mi >= mf) continue;
#pragma unroll
        for (int ni = 0; ni < 4; ni++) {
            int row = m0 + wm * 16 * mf + mi * 16 + (lane >> 2);
            int col = n0 + wn * 32 + ni * 8 + ((lane & 3) << 1);
            store_out(out, row,     col,     acc[mi][ni][0]);
            store_out(out, row,     col + 1, acc[mi][ni][1]);
            store_out(out, row + 8, col,     acc[mi][ni][2]);
            store_out(out, row + 8, col + 1, acc[mi][ni][3]);
        }
    }
}

// ---------------- launch ----------------
extern "C" void kernel_launch(void* const* d_in, const int* in_sizes, int n_in,
                              void* d_out, int out_size) {
    const float* z1 = (const float*)d_in[0];
    const float* z2 = (const float*)d_in[1];
    float* out = (float*)d_out;

    cudaFuncSetAttribute(gemm_qk_kernel,
                         cudaFuncAttributeMaxDynamicSharedMemorySize, SMEM_BYTES);
    cudaFuncSetAttribute(gemm_av_kernel,
                         cudaFuncAttributeMaxDynamicSharedMemorySize, SMEM_BYTES);

    build_q_kernel<<<800, 256>>>(z1);
    build_kv_kernel<<<28160, 256>>>(z2);
    gemm_qk_kernel<<<dim3(NPAD / BN, 3), 128, SMEM_BYTES>>>();   // rows {0-63,64-127,128-159}
    softmax_kernel<<<M, 512>>>();
    gemm_av_kernel<<<dim3(D / BN, 3), 128, SMEM_BYTES>>>(out);
}

// round 8
// speedup vs baseline: 1.0619x; 1.0458x over previous
#include <cuda_runtime.h>
#include <cuda_fp16.h>
#include <cstdint>

// ---------------- problem constants ----------------
constexpr int KC = 128, KH = 10, KW = 4;
constexpr int H = 100, W = 64;
constexpr int NH = 10, NW = 16;
constexpr int M = NH * NW;                 // 160 q rows
constexpr int MPAD = 192;                  // padded to 3*64 (pad rows zero)
constexpr int HK = H - KH + 1;             // 91
constexpr int WK = W - KW + 1;             // 61
constexpr int NKV = HK * WK;               // 5551
constexpr int NPAD = 5632;                 // 44*128
constexpr int D = KC * KH * KW;            // 5120

// ---------------- scratch ----------------
__device__ __half g_kv[(size_t)NPAD * D];      // [n][d] d-contig
__device__ __half g_q[MPAD * D];               // rows 160..191 stay zero
__device__ float  g_scores[MPAD * NPAD];
__device__ __half g_attn[MPAD * NPAD];         // rows 160..191 stay zero

// ---------------- ptx helpers ----------------
__device__ __forceinline__ uint32_t smem_u32(const void* p) {
    return (uint32_t)__cvta_generic_to_shared(p);
}
__device__ __forceinline__ void ldsm_x4(uint32_t& r0, uint32_t& r1, uint32_t& r2,
                                        uint32_t& r3, uint32_t a) {
    asm volatile("ldmatrix.sync.aligned.m8n8.x4.shared.b16 {%0,%1,%2,%3}, [%4];"
                 : "=r"(r0), "=r"(r1), "=r"(r2), "=r"(r3) : "r"(a));
}
__device__ __forceinline__ void ldsm_x4_t(uint32_t& r0, uint32_t& r1, uint32_t& r2,
                                          uint32_t& r3, uint32_t a) {
    asm volatile("ldmatrix.sync.aligned.m8n8.x4.trans.shared.b16 {%0,%1,%2,%3}, [%4];"
                 : "=r"(r0), "=r"(r1), "=r"(r2), "=r"(r3) : "r"(a));
}
__device__ __forceinline__ void mma16816(float* c, const uint32_t* a, const uint32_t* b) {
    asm volatile("mma.sync.aligned.m16n8k16.row.col.f32.f16.f16.f32 "
                 "{%0,%1,%2,%3}, {%4,%5,%6,%7}, {%8,%9}, {%0,%1,%2,%3};"
                 : "+f"(c[0]), "+f"(c[1]), "+f"(c[2]), "+f"(c[3])
                 : "r"(a[0]), "r"(a[1]), "r"(a[2]), "r"(a[3]),
                   "r"(b[0]), "r"(b[1]));
}
__device__ __forceinline__ void cpasync16(uint32_t s, const void* g) {
    asm volatile("cp.async.cg.shared.global [%0], [%1], 16;" :: "r"(s), "l"(g));
}
#define CP_COMMIT() asm volatile("cp.async.commit_group;")
#define CP_WAIT(n)  asm volatile("cp.async.wait_group %0;" :: "n"(n))

// ---------------- kernel 1: expand z2 -> kv fp16 ----------------
__global__ void build_kv_kernel(const float* __restrict__ z2) {
    constexpr int TOTAL = NKV * KC * KH;
    constexpr int PADG  = (NPAD - NKV) * (D / 4);
    int idx = blockIdx.x * blockDim.x + threadIdx.x;
    if (idx < TOTAL) {
        int n   = idx / (KC * KH);
        int rem = idx - n * (KC * KH);
        int c   = rem / KH;
        int i   = rem - c * KH;
        int h   = n / WK;
        int w   = n - h * WK;
        const float* src = z2 + (c * H + h + i) * W + w;
        __half2 p0 = __floats2half2_rn(src[0], src[1]);
        __half2 p1 = __floats2half2_rn(src[2], src[3]);
        uint2 v;
        v.x = *reinterpret_cast<uint32_t*>(&p0);
        v.y = *reinterpret_cast<uint32_t*>(&p1);
        *reinterpret_cast<uint2*>(&g_kv[(size_t)n * D + (c * KH + i) * KW]) = v;
    } else if (idx < TOTAL + PADG) {
        int p   = idx - TOTAL;
        int pr  = p / (D / 4);
        int off = (p - pr * (D / 4)) * 4;
        *reinterpret_cast<uint2*>(&g_kv[(size_t)(NKV + pr) * D + off]) = make_uint2(0u, 0u);
    }
}

// ---------------- kernel 2: q patches -> fp16 ----------------
__global__ void build_q_kernel(const float* __restrict__ z1) {
    constexpr int TOTAL = M * KC * KH;
    int idx = blockIdx.x * blockDim.x + threadIdx.x;
    if (idx >= TOTAL) return;
    int m   = idx / (KC * KH);
    int rem = idx - m * (KC * KH);
    int c   = rem / KH;
    int i   = rem - c * KH;
    int ih  = m >> 4;
    int iw  = m & 15;
    const float4 f = *reinterpret_cast<const float4*>(
        z1 + (c * H + ih * KH + i) * W + iw * KW);
    __half2 p0 = __floats2half2_rn(f.x, f.y);
    __half2 p1 = __floats2half2_rn(f.z, f.w);
    uint2 v;
    v.x = *reinterpret_cast<uint32_t*>(&p0);
    v.y = *reinterpret_cast<uint32_t*>(&p1);
    *reinterpret_cast<uint2*>(&g_q[m * D + (c * KH + i) * KW]) = v;
}

// ------- GEMM tiling: CTA 64(M) x 128(N), 4 warps 2x2, warp tile 32x64 -------
constexpr int BM  = 64;
constexpr int BN  = 128;
constexpr int BK  = 64;
constexpr int LDSA = 72;                        // k-contig rows (64 halves + pad)
constexpr int LDSB = 136;                       // av B rows (128 halves + pad)
constexpr int A_H  = BM * LDSA;                 // 4608
constexpr int B1_H = BN * LDSA;                 // 9216 (qk B: 128 n-rows x 64 k)
constexpr int STG_H = A_H + B1_H;               // 13824 halves (covers B2 = 8704 too)
constexpr int STAGES = 3;
constexpr int SMEM_BYTES = STAGES * STG_H * 2;  // 82944

// ---------------- kernel 3: scores = (q @ kv^T) / D ----------------
__global__ __launch_bounds__(128, 2) void gemm_qk_kernel() {
    extern __shared__ __align__(16) __half sm[];
    const int n0   = blockIdx.x * BN;
    const int m0   = blockIdx.y * BM;
    const int tid  = threadIdx.x;
    const int warp = tid >> 5, lane = tid & 31;
    const int wm = warp >> 1, wn = warp & 1;
    constexpr int KT = D / BK;                   // 80

    auto load_stage = [&](int s, int kt) {
        const int k0 = kt * BK;
        __half* As = sm + s * STG_H;
        __half* Bs = As + A_H;
#pragma unroll
        for (int i = 0; i < 4; i++) {            // A: 512 chunks
            int t = tid + i * 128;
            int r = t >> 3, c8 = (t & 7) << 3;
            cpasync16(smem_u32(&As[r * LDSA + c8]),
                      &g_q[(m0 + r) * D + k0 + c8]);
        }
#pragma unroll
        for (int i = 0; i < 8; i++) {            // B: 1024 chunks
            int t = tid + i * 128;
            int r = t >> 3, c8 = (t & 7) << 3;
            cpasync16(smem_u32(&Bs[r * LDSA + c8]),
                      &g_kv[(size_t)(n0 + r) * D + k0 + c8]);
        }
    };

    load_stage(0, 0); CP_COMMIT();
    load_stage(1, 1); CP_COMMIT();

    float acc[2][8][4] = {};

    for (int kt = 0; kt < KT; kt++) {
        if (kt < KT - 2) { CP_WAIT(1); } else { CP_WAIT(0); }
        __syncthreads();
        const int nxt = kt + 2;
        if (nxt < KT) { load_stage(nxt % 3, nxt); CP_COMMIT(); }

        const __half* As = sm + (kt % 3) * STG_H;
        const __half* Bs = As + A_H;
#pragma unroll
        for (int ks = 0; ks < BK / 16; ks++) {
            uint32_t a[2][4], b[8][2];
#pragma unroll
            for (int mi = 0; mi < 2; mi++) {
                int r = wm * 32 + mi * 16 + (lane & 15);
                int c = ks * 16 + (lane >> 4) * 8;
                ldsm_x4(a[mi][0], a[mi][1], a[mi][2], a[mi][3],
                        smem_u32(&As[r * LDSA + c]));
            }
#pragma unroll
            for (int nb = 0; nb < 4; nb++) {
                int r = wn * 64 + nb * 16 + (lane & 7) + (lane >> 4) * 8;
                int c = ks * 16 + ((lane >> 3) & 1) * 8;
                uint32_t r0, r1, r2, r3;
                ldsm_x4(r0, r1, r2, r3, smem_u32(&Bs[r * LDSA + c]));
                b[nb * 2][0] = r0; b[nb * 2][1] = r1;
                b[nb * 2 + 1][0] = r2; b[nb * 2 + 1][1] = r3;
            }
#pragma unroll
            for (int mi = 0; mi < 2; mi++)
#pragma unroll
                for (int ni = 0; ni < 8; ni++)
                    mma16816(acc[mi][ni], a[mi], b[ni]);
        }
    }

    const float scale = 1.0f / (float)D;
#pragma unroll
    for (int mi = 0; mi < 2; mi++)
#pragma unroll
        for (int ni = 0; ni < 8; ni++) {
            int row = m0 + wm * 32 + mi * 16 + (lane >> 2);
            int col = n0 + wn * 64 + ni * 8 + ((lane & 3) << 1);
            g_scores[row * NPAD + col]           = acc[mi][ni][0] * scale;
            g_scores[row * NPAD + col + 1]       = acc[mi][ni][1] * scale;
            g_scores[(row + 8) * NPAD + col]     = acc[mi][ni][2] * scale;
            g_scores[(row + 8) * NPAD + col + 1] = acc[mi][ni][3] * scale;
        }
}

// ---------------- kernel 4: row softmax ----------------
__global__ __launch_bounds__(512) void softmax_kernel() {
    __shared__ float row[NPAD];
    __shared__ float red[512];
    const int m   = blockIdx.x;
    const int tid = threadIdx.x;

    float mx = -1e30f;
    for (int n = tid; n < NKV; n += 512) {
        float v = g_scores[m * NPAD + n];
        row[n] = v;
        mx = fmaxf(mx, v);
    }
    red[tid] = mx;
    __syncthreads();
    for (int s = 256; s > 0; s >>= 1) {
        if (tid < s) red[tid] = fmaxf(red[tid], red[tid + s]);
        __syncthreads();
    }
    const float smx = red[0];
    __syncthreads();

    float sum = 0.f;
    for (int n = tid; n < NKV; n += 512) {
        float e = __expf(row[n] - smx);
        row[n] = e;
        sum += e;
    }
    red[tid] = sum;
    __syncthreads();
    for (int s = 256; s > 0; s >>= 1) {
        if (tid < s) red[tid] += red[tid + s];
        __syncthreads();
    }
    const float inv = 1.0f / red[0];
    for (int n = tid; n < NPAD; n += 512)
        g_attn[m * NPAD + n] = (n < NKV) ? __float2half(row[n] * inv)
                                         : __float2half(0.f);
}

// ---------------- kernel 5: out = attn @ kv ----------------
__device__ __forceinline__ void store_out(float* __restrict__ out, int m, int d, float v) {
    if (m >= M) return;
    int c   = d / 40;
    int rem = d - c * 40;
    int i   = rem >> 2;
    int j   = rem & 3;
    int ih  = m >> 4;
    int iw  = m & 15;
    out[(c * H + ih * KH + i) * W + iw * KW + j] = v;
}

__global__ __launch_bounds__(128, 2) void gemm_av_kernel(float* __restrict__ out) {
    extern __shared__ __align__(16) __half sm[];
    const int n0   = blockIdx.x * BN;            // over D
    const int m0   = blockIdx.y * BM;
    const int tid  = threadIdx.x;
    const int warp = tid >> 5, lane = tid & 31;
    const int wm = warp >> 1, wn = warp & 1;
    constexpr int KT = NPAD / BK;                // 88

    auto load_stage = [&](int s, int kt) {
        const int k0 = kt * BK;
        __half* As = sm + s * STG_H;
        __half* Bs = As + A_H;
#pragma unroll
        for (int i = 0; i < 4; i++) {            // A: 512 chunks (k-contig)
            int t = tid + i * 128;
            int r = t >> 3, c8 = (t & 7) << 3;
            cpasync16(smem_u32(&As[r * LDSA + c8]),
                      &g_attn[(m0 + r) * NPAD + k0 + c8]);
        }
#pragma unroll
        for (int i = 0; i < 8; i++) {            // B: 64 k-rows x 16 chunks (n-contig)
            int t = tid + i * 128;
            int r = t >> 4, c8 = (t & 15) << 3;
            cpasync16(smem_u32(&Bs[r * LDSB + c8]),
                      &g_kv[(size_t)(k0 + r) * D + n0 + c8]);
        }
    };

    load_stage(0, 0); CP_COMMIT();
    load_stage(1, 1); CP_COMMIT();

    float acc[2][8][4] = {};

    for (int kt = 0; kt < KT; kt++) {
        if (kt < KT - 2) { CP_WAIT(1); } else { CP_WAIT(0); }
        __syncthreads();
        const int nxt = kt + 2;
        if (nxt < KT) { load_stage(nxt % 3, nxt); CP_COMMIT(); }

        const __half* As = sm + (kt % 3) * STG_H;
        const __half* Bs = As + A_H;
#pragma unroll
        for (int ks = 0; ks < BK / 16; ks++) {
            uint32_t a[2][4], b[8][2];
#pragma unroll
            for (int mi = 0; mi < 2; mi++) {
                int r = wm * 32 + mi * 16 + (lane & 15);
                int c = ks * 16 + (lane >> 4) * 8;
                ldsm_x4(a[mi][0], a[mi][1], a[mi][2], a[mi][3],
                        smem_u32(&As[r * LDSA + c]));
            }
#pragma unroll
            for (int nb = 0; nb < 4; nb++) {
                int r = ks * 16 + (lane & 7) + ((lane >> 3) & 1) * 8;
                int c = wn * 64 + nb * 16 + (lane >> 4) * 8;
                uint32_t r0, r1, r2, r3;
                ldsm_x4_t(r0, r1, r2, r3, smem_u32(&Bs[r * LDSB + c]));
                b[nb * 2][0] = r0; b[nb * 2][1] = r1;
                b[nb * 2 + 1][0] = r2; b[nb * 2 + 1][1] = r3;
            }
#pragma unroll
            for (int mi = 0; mi < 2; mi++)
#pragma unroll
                for (int ni = 0; ni < 8; ni++)
                    mma16816(acc[mi][ni], a[mi], b[ni]);
        }
    }

#pragma unroll
    for (int mi = 0; mi < 2; mi++)
#pragma unroll
        for (int ni = 0; ni < 8; ni++) {
            int row = m0 + wm * 32 + mi * 16 + (lane >> 2);
            int col = n0 + wn * 64 + ni * 8 + ((lane & 3) << 1);
            store_out(out, row,     col,     acc[mi][ni][0]);
            store_out(out, row,     col + 1, acc[mi][ni][1]);
            store_out(out, row + 8, col,     acc[mi][ni][2]);
            store_out(out, row + 8, col + 1, acc[mi][ni][3]);
        }
}

// ---------------- launch ----------------
extern "C" void kernel_launch(void* const* d_in, const int* in_sizes, int n_in,
                              void* d_out, int out_size) {
    const float* z1 = (const float*)d_in[0];
    const float* z2 = (const float*)d_in[1];
    float* out = (float*)d_out;

    cudaFuncSetAttribute(gemm_qk_kernel,
                         cudaFuncAttributeMaxDynamicSharedMemorySize, SMEM_BYTES);
    cudaFuncSetAttribute(gemm_av_kernel,
                         cudaFuncAttributeMaxDynamicSharedMemorySize, SMEM_BYTES);

    build_q_kernel<<<800, 256>>>(z1);
    build_kv_kernel<<<28160, 256>>>(z2);
    gemm_qk_kernel<<<dim3(NPAD / BN, MPAD / BM), 128, SMEM_BYTES>>>();   // 44x3 = 132
    softmax_kernel<<<M, 512>>>();
    gemm_av_kernel<<<dim3(D / BN, MPAD / BM), 128, SMEM_BYTES>>>(out);   // 40x3 = 120
}

// round 9
// speedup vs baseline: 1.1812x; 1.1123x over previous
#include <cuda_runtime.h>
#include <cuda_fp16.h>
#include <cstdint>

// ---------------- problem constants ----------------
constexpr int KC = 128, KH = 10, KW = 4;
constexpr int H = 100, W = 64;
constexpr int NH = 10, NW = 16;
constexpr int M = NH * NW;                 // 160 q rows (no padding anywhere)
constexpr int HK = H - KH + 1;             // 91
constexpr int WK = W - KW + 1;             // 61
constexpr int NKV = HK * WK;               // 5551
constexpr int NPAD = 5632;                 // 88*64
constexpr int D = KC * KH * KW;            // 5120

// ---------------- scratch ----------------
__device__ __half g_kv[(size_t)NPAD * D];      // [n][d] d-contig
__device__ __half g_q[M * D];
__device__ float  g_scores[M * NPAD];
__device__ __half g_attn[M * NPAD];

// ---------------- ptx helpers ----------------
__device__ __forceinline__ uint32_t smem_u32(const void* p) {
    return (uint32_t)__cvta_generic_to_shared(p);
}
__device__ __forceinline__ void ldsm_x4(uint32_t& r0, uint32_t& r1, uint32_t& r2,
                                        uint32_t& r3, uint32_t a) {
    asm volatile("ldmatrix.sync.aligned.m8n8.x4.shared.b16 {%0,%1,%2,%3}, [%4];"
                 : "=r"(r0), "=r"(r1), "=r"(r2), "=r"(r3) : "r"(a));
}
__device__ __forceinline__ void ldsm_x4_t(uint32_t& r0, uint32_t& r1, uint32_t& r2,
                                          uint32_t& r3, uint32_t a) {
    asm volatile("ldmatrix.sync.aligned.m8n8.x4.trans.shared.b16 {%0,%1,%2,%3}, [%4];"
                 : "=r"(r0), "=r"(r1), "=r"(r2), "=r"(r3) : "r"(a));
}
__device__ __forceinline__ void mma16816(float* c, const uint32_t* a, const uint32_t* b) {
    asm volatile("mma.sync.aligned.m16n8k16.row.col.f32.f16.f16.f32 "
                 "{%0,%1,%2,%3}, {%4,%5,%6,%7}, {%8,%9}, {%0,%1,%2,%3};"
                 : "+f"(c[0]), "+f"(c[1]), "+f"(c[2]), "+f"(c[3])
                 : "r"(a[0]), "r"(a[1]), "r"(a[2]), "r"(a[3]),
                   "r"(b[0]), "r"(b[1]));
}
__device__ __forceinline__ void cpasync16(uint32_t s, const void* g) {
    asm volatile("cp.async.cg.shared.global [%0], [%1], 16;" :: "r"(s), "l"(g));
}
#define CP_COMMIT() asm volatile("cp.async.commit_group;")
#define CP_WAIT(n)  asm volatile("cp.async.wait_group %0;" :: "n"(n))

// ---------------- kernel 1: expand z2 -> kv fp16 ----------------
__global__ void build_kv_kernel(const float* __restrict__ z2) {
    constexpr int TOTAL = NKV * KC * KH;
    constexpr int PADG  = (NPAD - NKV) * (D / 4);
    int idx = blockIdx.x * blockDim.x + threadIdx.x;
    if (idx < TOTAL) {
        int n   = idx / (KC * KH);
        int rem = idx - n * (KC * KH);
        int c   = rem / KH;
        int i   = rem - c * KH;
        int h   = n / WK;
        int w   = n - h * WK;
        const float* src = z2 + (c * H + h + i) * W + w;
        __half2 p0 = __floats2half2_rn(src[0], src[1]);
        __half2 p1 = __floats2half2_rn(src[2], src[3]);
        uint2 v;
        v.x = *reinterpret_cast<uint32_t*>(&p0);
        v.y = *reinterpret_cast<uint32_t*>(&p1);
        *reinterpret_cast<uint2*>(&g_kv[(size_t)n * D + (c * KH + i) * KW]) = v;
    } else if (idx < TOTAL + PADG) {
        int p   = idx - TOTAL;
        int pr  = p / (D / 4);
        int off = (p - pr * (D / 4)) * 4;
        *reinterpret_cast<uint2*>(&g_kv[(size_t)(NKV + pr) * D + off]) = make_uint2(0u, 0u);
    }
}

// ---------------- kernel 2: q patches -> fp16 ----------------
__global__ void build_q_kernel(const float* __restrict__ z1) {
    constexpr int TOTAL = M * KC * KH;
    int idx = blockIdx.x * blockDim.x + threadIdx.x;
    if (idx >= TOTAL) return;
    int m   = idx / (KC * KH);
    int rem = idx - m * (KC * KH);
    int c   = rem / KH;
    int i   = rem - c * KH;
    int ih  = m >> 4;
    int iw  = m & 15;
    const float4 f = *reinterpret_cast<const float4*>(
        z1 + (c * H + ih * KH + i) * W + iw * KW);
    __half2 p0 = __floats2half2_rn(f.x, f.y);
    __half2 p1 = __floats2half2_rn(f.z, f.w);
    uint2 v;
    v.x = *reinterpret_cast<uint32_t*>(&p0);
    v.y = *reinterpret_cast<uint32_t*>(&p1);
    *reinterpret_cast<uint2*>(&g_q[m * D + (c * KH + i) * KW]) = v;
}

// -------- GEMM tiling: CTA 32(M) x 64(N), 64 threads = 2 warps (32x32 each) ----
constexpr int BM  = 32;
constexpr int BN  = 64;
constexpr int BK  = 64;
constexpr int LDS = 72;
constexpr int STAGES = 4;
constexpr int A_HALVES = BM * LDS;               // 2304
constexpr int B_HALVES = BN * LDS;               // 4608
constexpr int STAGE_HALVES = A_HALVES + B_HALVES;
constexpr int SMEM_BYTES = STAGES * STAGE_HALVES * 2;   // 55296

// ---------------- kernel 3: scores = (q @ kv^T) / D ----------------
__global__ __launch_bounds__(64, 4) void gemm_qk_kernel() {
    extern __shared__ __align__(16) __half sm[];
    const int n0   = blockIdx.x * BN;
    const int m0   = blockIdx.y * BM;
    const int tid  = threadIdx.x;
    const int wn   = tid >> 5, lane = tid & 31;  // 2 warps side by side in N
    constexpr int KT = D / BK;                   // 80

    auto load_stage = [&](int s, int kt) {
        const int k0 = kt * BK;
        __half* As = sm + s * STAGE_HALVES;
        __half* Bs = As + A_HALVES;
#pragma unroll
        for (int i = 0; i < 4; i++) {            // A: 256 chunks / 64 thr
            int t = tid + i * 64;
            int r = t >> 3, c8 = (t & 7) << 3;
            cpasync16(smem_u32(&As[r * LDS + c8]),
                      &g_q[(m0 + r) * D + k0 + c8]);
        }
#pragma unroll
        for (int i = 0; i < 8; i++) {            // B: 512 chunks
            int t = tid + i * 64;
            int r = t >> 3, c8 = (t & 7) << 3;
            cpasync16(smem_u32(&Bs[r * LDS + c8]),
                      &g_kv[(size_t)(n0 + r) * D + k0 + c8]);
        }
    };

#pragma unroll
    for (int s = 0; s < STAGES - 1; s++) { load_stage(s, s); CP_COMMIT(); }

    float acc[2][4][4] = {};

    for (int kt = 0; kt < KT; kt++) {
        CP_WAIT(STAGES - 2);
        __syncthreads();
        int nxt = kt + STAGES - 1;
        if (nxt < KT) load_stage(nxt & (STAGES - 1), nxt);
        CP_COMMIT();

        const __half* As = sm + (kt & (STAGES - 1)) * STAGE_HALVES;
        const __half* Bs = As + A_HALVES;
#pragma unroll
        for (int ks = 0; ks < BK / 16; ks++) {
            uint32_t a[2][4], b[4][2];
#pragma unroll
            for (int mi = 0; mi < 2; mi++) {
                int r = mi * 16 + (lane & 15);
                int c = ks * 16 + (lane >> 4) * 8;
                ldsm_x4(a[mi][0], a[mi][1], a[mi][2], a[mi][3],
                        smem_u32(&As[r * LDS + c]));
            }
#pragma unroll
            for (int nb = 0; nb < 2; nb++) {
                int r = wn * 32 + nb * 16 + (lane & 7) + (lane >> 4) * 8;
                int c = ks * 16 + ((lane >> 3) & 1) * 8;
                uint32_t r0, r1, r2, r3;
                ldsm_x4(r0, r1, r2, r3, smem_u32(&Bs[r * LDS + c]));
                b[nb * 2][0] = r0; b[nb * 2][1] = r1;
                b[nb * 2 + 1][0] = r2; b[nb * 2 + 1][1] = r3;
            }
#pragma unroll
            for (int mi = 0; mi < 2; mi++)
#pragma unroll
                for (int ni = 0; ni < 4; ni++)
                    mma16816(acc[mi][ni], a[mi], b[ni]);
        }
    }

    const float scale = 1.0f / (float)D;
#pragma unroll
    for (int mi = 0; mi < 2; mi++)
#pragma unroll
        for (int ni = 0; ni < 4; ni++) {
            int row = m0 + mi * 16 + (lane >> 2);
            int col = n0 + wn * 32 + ni * 8 + ((lane & 3) << 1);
            g_scores[row * NPAD + col]           = acc[mi][ni][0] * scale;
            g_scores[row * NPAD + col + 1]       = acc[mi][ni][1] * scale;
            g_scores[(row + 8) * NPAD + col]     = acc[mi][ni][2] * scale;
            g_scores[(row + 8) * NPAD + col + 1] = acc[mi][ni][3] * scale;
        }
}

// ---------------- kernel 4: row softmax ----------------
__global__ __launch_bounds__(512) void softmax_kernel() {
    __shared__ float row[NPAD];
    __shared__ float red[512];
    const int m   = blockIdx.x;
    const int tid = threadIdx.x;

    float mx = -1e30f;
    for (int n = tid; n < NKV; n += 512) {
        float v = g_scores[m * NPAD + n];
        row[n] = v;
        mx = fmaxf(mx, v);
    }
    red[tid] = mx;
    __syncthreads();
    for (int s = 256; s > 0; s >>= 1) {
        if (tid < s) red[tid] = fmaxf(red[tid], red[tid + s]);
        __syncthreads();
    }
    const float smx = red[0];
    __syncthreads();

    float sum = 0.f;
    for (int n = tid; n < NKV; n += 512) {
        float e = __expf(row[n] - smx);
        row[n] = e;
        sum += e;
    }
    red[tid] = sum;
    __syncthreads();
    for (int s = 256; s > 0; s >>= 1) {
        if (tid < s) red[tid] += red[tid + s];
        __syncthreads();
    }
    const float inv = 1.0f / red[0];
    for (int n = tid; n < NPAD; n += 512)
        g_attn[m * NPAD + n] = (n < NKV) ? __float2half(row[n] * inv)
                                         : __float2half(0.f);
}

// ---------------- kernel 5: out = attn @ kv ----------------
__device__ __forceinline__ void store_out(float* __restrict__ out, int m, int d, float v) {
    int c   = d / 40;
    int rem = d - c * 40;
    int i   = rem >> 2;
    int j   = rem & 3;
    int ih  = m >> 4;
    int iw  = m & 15;
    out[(c * H + ih * KH + i) * W + iw * KW + j] = v;
}

__global__ __launch_bounds__(64, 4) void gemm_av_kernel(float* __restrict__ out) {
    extern __shared__ __align__(16) __half sm[];
    const int n0   = blockIdx.x * BN;            // over D
    const int m0   = blockIdx.y * BM;
    const int tid  = threadIdx.x;
    const int wn   = tid >> 5, lane = tid & 31;
    constexpr int KT = NPAD / BK;                // 88

    auto load_stage = [&](int s, int kt) {
        const int k0 = kt * BK;
        __half* As = sm + s * STAGE_HALVES;
        __half* Bs = As + A_HALVES;
#pragma unroll
        for (int i = 0; i < 4; i++) {            // A: 256 chunks (k-contig rows)
            int t = tid + i * 64;
            int r = t >> 3, c8 = (t & 7) << 3;
            cpasync16(smem_u32(&As[r * LDS + c8]),
                      &g_attn[(m0 + r) * NPAD + k0 + c8]);
        }
#pragma unroll
        for (int i = 0; i < 8; i++) {            // B: 64 k-rows x 8 chunks (n-contig)
            int t = tid + i * 64;
            int r = t >> 3, c8 = (t & 7) << 3;
            cpasync16(smem_u32(&Bs[r * LDS + c8]),
                      &g_kv[(size_t)(k0 + r) * D + n0 + c8]);
        }
    };

#pragma unroll
    for (int s = 0; s < STAGES - 1; s++) { load_stage(s, s); CP_COMMIT(); }

    float acc[2][4][4] = {};

    for (int kt = 0; kt < KT; kt++) {
        CP_WAIT(STAGES - 2);
        __syncthreads();
        int nxt = kt + STAGES - 1;
        if (nxt < KT) load_stage(nxt & (STAGES - 1), nxt);
        CP_COMMIT();

        const __half* As = sm + (kt & (STAGES - 1)) * STAGE_HALVES;
        const __half* Bs = As + A_HALVES;
#pragma unroll
        for (int ks = 0; ks < BK / 16; ks++) {
            uint32_t a[2][4], b[4][2];
#pragma unroll
            for (int mi = 0; mi < 2; mi++) {
                int r = mi * 16 + (lane & 15);
                int c = ks * 16 + (lane >> 4) * 8;
                ldsm_x4(a[mi][0], a[mi][1], a[mi][2], a[mi][3],
                        smem_u32(&As[r * LDS + c]));
            }
#pragma unroll
            for (int nb = 0; nb < 2; nb++) {
                int r = ks * 16 + (lane & 7) + ((lane >> 3) & 1) * 8;
                int c = wn * 32 + nb * 16 + (lane >> 4) * 8;
                uint32_t r0, r1, r2, r3;
                ldsm_x4_t(r0, r1, r2, r3, smem_u32(&Bs[r * LDS + c]));
                b[nb * 2][0] = r0; b[nb * 2][1] = r1;
                b[nb * 2 + 1][0] = r2; b[nb * 2 + 1][1] = r3;
            }
#pragma unroll
            for (int mi = 0; mi < 2; mi++)
#pragma unroll
                for (int ni = 0; ni < 4; ni++)
                    mma16816(acc[mi][ni], a[mi], b[ni]);
        }
    }

#pragma unroll
    for (int mi = 0; mi < 2; mi++)
#pragma unroll
        for (int ni = 0; ni < 4; ni++) {
            int row = m0 + mi * 16 + (lane >> 2);
            int col = n0 + wn * 32 + ni * 8 + ((lane & 3) << 1);
            store_out(out, row,     col,     acc[mi][ni][0]);
            store_out(out, row,     col + 1, acc[mi][ni][1]);
            store_out(out, row + 8, col,     acc[mi][ni][2]);
            store_out(out, row + 8, col + 1, acc[mi][ni][3]);
        }
}

// ---------------- launch ----------------
extern "C" void kernel_launch(void* const* d_in, const int* in_sizes, int n_in,
                              void* d_out, int out_size) {
    const float* z1 = (const float*)d_in[0];
    const float* z2 = (const float*)d_in[1];
    float* out = (float*)d_out;

    cudaFuncSetAttribute(gemm_qk_kernel,
                         cudaFuncAttributeMaxDynamicSharedMemorySize, SMEM_BYTES);
    cudaFuncSetAttribute(gemm_av_kernel,
                         cudaFuncAttributeMaxDynamicSharedMemorySize, SMEM_BYTES);

    build_q_kernel<<<800, 256>>>(z1);
    build_kv_kernel<<<28160, 256>>>(z2);
    gemm_qk_kernel<<<dim3(NPAD / BN, M / BM), 64, SMEM_BYTES>>>();   // 88x5 = 440
    softmax_kernel<<<M, 512>>>();
    gemm_av_kernel<<<dim3(D / BN, M / BM), 64, SMEM_BYTES>>>(out);   // 80x5 = 400
}